// round 1
// baseline (speedup 1.0000x reference)
#include <cuda_runtime.h>
#include <math.h>

// Problem constants
#define CB   4
#define CS   1024
#define CDM  1024
#define CH   16
#define CDK  64
#define CBH  (CB*CH)

// ---------------- scratch (device globals: allocation-free) ----------------
__device__ float g_qh[(size_t)CB*CH*CS*CDK];       // 16 MB
__device__ float g_kh[(size_t)CB*CH*CS*CDK];       // 16 MB
__device__ float g_vh[(size_t)CB*CH*CS*CDK];       // 16 MB
__device__ float g_scores[(size_t)CBH*CS*CS];      // 256 MB
__device__ float g_concat[(size_t)CB*CS*CDM];      // 16 MB

// ============================================================================
// GEMM NT: C[m,n] = alpha * dot(A[m,:K], B[n,:K]) (+ bias[n])
// 128x128 tile, BK=8, 256 threads, 8x8 per thread.
// OUT_MODE 0: C row-major [M,N] (ldc = N).
// OUT_MODE 1: head-scatter: m=(b,s), n=(h,dk) -> [(b*H+h)*S+s]*DK+dk
// Batched via blockIdx.z with strides sA,sB,sC.
// Requires M%128==0, N%128==0, K%8==0, K>=8.
// ============================================================================
template<int OUT_MODE>
__global__ void __launch_bounds__(256) gemm_nt_kernel(
    const float* __restrict__ A, const float* __restrict__ B,
    const float* __restrict__ bias, float* __restrict__ C,
    int M, int N, int K, float alpha,
    long sA, long sB, long sC)
{
    A += (long)blockIdx.z * sA;
    B += (long)blockIdx.z * sB;
    C += (long)blockIdx.z * sC;
    const int m0 = blockIdx.y * 128;
    const int n0 = blockIdx.x * 128;

    __shared__ float As[8][128];
    __shared__ float Bs[8][128];

    const int tid  = threadIdx.x;
    const int lrow = tid >> 1;          // 0..127
    const int lk4  = (tid & 1) << 2;    // 0 or 4
    const int tx   = tid & 15;
    const int ty   = tid >> 4;

    float acc[8][8];
    #pragma unroll
    for (int i = 0; i < 8; i++)
        #pragma unroll
        for (int j = 0; j < 8; j++) acc[i][j] = 0.f;

    const float* Ap = A + (long)(m0 + lrow) * K + lk4;
    const float* Bp = B + (long)(n0 + lrow) * K + lk4;

    for (int k0 = 0; k0 < K; k0 += 8) {
        float4 a4 = *(const float4*)(Ap + k0);
        float4 b4 = *(const float4*)(Bp + k0);
        As[lk4+0][lrow] = a4.x; As[lk4+1][lrow] = a4.y;
        As[lk4+2][lrow] = a4.z; As[lk4+3][lrow] = a4.w;
        Bs[lk4+0][lrow] = b4.x; Bs[lk4+1][lrow] = b4.y;
        Bs[lk4+2][lrow] = b4.z; Bs[lk4+3][lrow] = b4.w;
        __syncthreads();
        #pragma unroll
        for (int kk = 0; kk < 8; kk++) {
            float a[8], b[8];
            *(float4*)&a[0] = *(const float4*)&As[kk][ty*4];
            *(float4*)&a[4] = *(const float4*)&As[kk][64 + ty*4];
            *(float4*)&b[0] = *(const float4*)&Bs[kk][tx*4];
            *(float4*)&b[4] = *(const float4*)&Bs[kk][64 + tx*4];
            #pragma unroll
            for (int i = 0; i < 8; i++)
                #pragma unroll
                for (int j = 0; j < 8; j++)
                    acc[i][j] += a[i] * b[j];
        }
        __syncthreads();
    }

    #pragma unroll
    for (int i = 0; i < 8; i++) {
        int m = m0 + ((i < 4) ? (ty*4 + i) : (64 + ty*4 + i - 4));
        #pragma unroll
        for (int j = 0; j < 8; j++) {
            int n = n0 + ((j < 4) ? (tx*4 + j) : (64 + tx*4 + j - 4));
            float v = acc[i][j] * alpha;
            if (bias) v += bias[n];
            if (OUT_MODE == 0) {
                C[(long)m * N + n] = v;
            } else {
                int b_ = m >> 10;              // m / S   (S = 1024)
                int s  = m & 1023;             // m % S
                int h  = n >> 6;               // n / DK  (DK = 64)
                int dk = n & 63;
                C[(((long)(b_*CH + h)) * CS + s) * CDK + dk] = v;
            }
        }
    }
}

// ============================================================================
// attn @ V (NN): per bh: C[i,d] = sum_j P[i,j] * V[j,d]
// P: [S,S] row-major; V: [S,64] row-major.  Tile 128x64, BK=16, 256 threads,
// 8x4 per thread.  Output written directly into concat layout
// g_concat[b, i, h*64 + d].
// ============================================================================
__global__ void __launch_bounds__(256) gemm_av_kernel(
    const float* __restrict__ P, const float* __restrict__ V,
    float* __restrict__ Cc)
{
    const int z = blockIdx.z;                       // bh
    const float* Pz = P + (long)z * CS * CS;
    const float* Vz = V + (long)z * CS * CDK;
    const int m0 = blockIdx.y * 128;

    __shared__ float As[16][128];
    __shared__ float Bs[16][64];

    const int tid  = threadIdx.x;
    const int tx   = tid & 15;
    const int ty   = tid >> 4;
    const int arow = tid >> 2;          // 0..63
    const int ak4  = (tid & 3) << 2;    // 0,4,8,12
    const int brow = tid >> 4;          // 0..15
    const int bn4  = (tid & 15) << 2;   // 0..60

    float acc[8][4];
    #pragma unroll
    for (int i = 0; i < 8; i++)
        #pragma unroll
        for (int j = 0; j < 4; j++) acc[i][j] = 0.f;

    for (int k0 = 0; k0 < CS; k0 += 16) {
        float4 a0 = *(const float4*)(Pz + (long)(m0 + arow)      * CS + k0 + ak4);
        float4 a1 = *(const float4*)(Pz + (long)(m0 + arow + 64) * CS + k0 + ak4);
        float4 b0 = *(const float4*)(Vz + (long)(k0 + brow) * CDK + bn4);
        As[ak4+0][arow]    = a0.x; As[ak4+1][arow]    = a0.y;
        As[ak4+2][arow]    = a0.z; As[ak4+3][arow]    = a0.w;
        As[ak4+0][arow+64] = a1.x; As[ak4+1][arow+64] = a1.y;
        As[ak4+2][arow+64] = a1.z; As[ak4+3][arow+64] = a1.w;
        *(float4*)&Bs[brow][bn4] = b0;
        __syncthreads();
        #pragma unroll
        for (int kk = 0; kk < 16; kk++) {
            float a[8], b[4];
            *(float4*)&a[0] = *(const float4*)&As[kk][ty*4];
            *(float4*)&a[4] = *(const float4*)&As[kk][64 + ty*4];
            *(float4*)&b[0] = *(const float4*)&Bs[kk][tx*4];
            #pragma unroll
            for (int i = 0; i < 8; i++)
                #pragma unroll
                for (int j = 0; j < 4; j++)
                    acc[i][j] += a[i] * b[j];
        }
        __syncthreads();
    }

    const int b_ = z >> 4;     // z / H
    const int h  = z & 15;     // z % H
    #pragma unroll
    for (int i = 0; i < 8; i++) {
        int m = m0 + ((i < 4) ? (ty*4 + i) : (64 + ty*4 + i - 4));
        float* outp = Cc + ((long)(b_*CS + m)) * CDM + h * CDK;
        #pragma unroll
        for (int j = 0; j < 4; j++)
            outp[tx*4 + j] = acc[i][j];
    }
}

// ============================================================================
// Row-ops: for each (bh, i) row of scores (length S=1024):
//   1) m = max_j s_j   (over ALL j — reference softmaxes unmasked scores)
//   2) e_j = exp(s_j - m), Z = sum_j e_j
//   3) masked inclusive cumsum c_j of e_j * [j<=i], T = total
//   4) rem = (T - c_j)/Z; dist = sqrt(max(rem*(i-j), 0));
//      eff = clip(exp(-softplus(g_h)*dist), 1e-5, 1e5); s'_j = s_j*eff (j<=i)
//      s'_j = -inf (j>i)
//   5) second softmax of s'; write back in place.
// One CTA (256 threads) per row; 4 contiguous elements per thread.
// ============================================================================
__global__ void __launch_bounds__(256) rowops_kernel(
    float* __restrict__ scores, const float* __restrict__ gammas)
{
    const long gid = blockIdx.x;              // 0 .. CBH*CS-1
    const int  i   = (int)(gid & (CS - 1));
    const int  bh  = (int)(gid >> 10);
    const int  h   = bh & (CH - 1);
    float* row = scores + gid * CS;

    const int tid  = threadIdx.x;
    const int lane = tid & 31;
    const int warp = tid >> 5;
    const int jb   = tid << 2;

    __shared__ float sm[64];

    float4 sv = *(const float4*)(row + jb);
    float s0 = sv.x, s1 = sv.y, s2 = sv.z, s3 = sv.w;

    // ---- 1) block max over all j ----
    float mx = fmaxf(fmaxf(s0, s1), fmaxf(s2, s3));
    #pragma unroll
    for (int o = 16; o; o >>= 1) mx = fmaxf(mx, __shfl_xor_sync(0xffffffffu, mx, o));
    if (lane == 0) sm[warp] = mx;
    __syncthreads();
    if (tid == 0) {
        float t = sm[0];
        #pragma unroll
        for (int w = 1; w < 8; w++) t = fmaxf(t, sm[w]);
        sm[32] = t;
    }
    __syncthreads();
    const float m = sm[32];

    // ---- 2) exp and full sum Z ----
    float e0 = expf(s0 - m), e1 = expf(s1 - m), e2 = expf(s2 - m), e3 = expf(s3 - m);
    float zl = e0 + e1 + e2 + e3;
    #pragma unroll
    for (int o = 16; o; o >>= 1) zl += __shfl_xor_sync(0xffffffffu, zl, o);
    __syncthreads();                    // sm[0..7] reuse barrier
    if (lane == 0) sm[warp] = zl;
    __syncthreads();
    if (tid == 0) { float t = 0.f; for (int w = 0; w < 8; w++) t += sm[w]; sm[33] = t; }

    // ---- 3) masked inclusive prefix sum (block scan) ----
    float me0 = (jb + 0 <= i) ? e0 : 0.f;
    float me1 = (jb + 1 <= i) ? e1 : 0.f;
    float me2 = (jb + 2 <= i) ? e2 : 0.f;
    float me3 = (jb + 3 <= i) ? e3 : 0.f;
    float c0 = me0, c1 = c0 + me1, c2 = c1 + me2, c3 = c2 + me3;
    float x = c3;
    #pragma unroll
    for (int d = 1; d < 32; d <<= 1) {
        float y = __shfl_up_sync(0xffffffffu, x, d);
        if (lane >= d) x += y;
    }
    if (lane == 31) sm[16 + warp] = x;    // warp totals (disjoint from sm[0..7])
    __syncthreads();
    if (tid == 0) {
        float a = 0.f;
        #pragma unroll
        for (int w = 0; w < 8; w++) { float t = sm[16 + w]; sm[24 + w] = a; a += t; }
        sm[34] = a;                        // T (masked total, unnormalized)
    }
    __syncthreads();
    const float Z     = sm[33];
    const float T     = sm[34];
    const float carry = sm[24 + warp] + (x - c3);   // exclusive prefix before thread
    c0 += carry; c1 += carry; c2 += carry; c3 += carry;

    // ---- 4) distance decay ----
    const float g     = gammas[h];
    const float gamma = -((g > 20.f) ? g : log1pf(expf(g)));   // -softplus
    const float invZ  = 1.f / Z;
    const float NEG_INF = -__int_as_float(0x7f800000);

    float n0, n1, n2, n3;
    {
        int j;
        j = jb + 0;
        if (j <= i) {
            float d2 = fmaxf((T - c0) * invZ * (float)(i - j), 0.f);
            float eff = fminf(fmaxf(expf(gamma * sqrtf(d2)), 1e-5f), 1e5f);
            n0 = s0 * eff;
        } else n0 = NEG_INF;
        j = jb + 1;
        if (j <= i) {
            float d2 = fmaxf((T - c1) * invZ * (float)(i - j), 0.f);
            float eff = fminf(fmaxf(expf(gamma * sqrtf(d2)), 1e-5f), 1e5f);
            n1 = s1 * eff;
        } else n1 = NEG_INF;
        j = jb + 2;
        if (j <= i) {
            float d2 = fmaxf((T - c2) * invZ * (float)(i - j), 0.f);
            float eff = fminf(fmaxf(expf(gamma * sqrtf(d2)), 1e-5f), 1e5f);
            n2 = s2 * eff;
        } else n2 = NEG_INF;
        j = jb + 3;
        if (j <= i) {
            float d2 = fmaxf((T - c3) * invZ * (float)(i - j), 0.f);
            float eff = fminf(fmaxf(expf(gamma * sqrtf(d2)), 1e-5f), 1e5f);
            n3 = s3 * eff;
        } else n3 = NEG_INF;
    }

    // ---- 5) second (masked) softmax ----
    float mx2 = fmaxf(fmaxf(n0, n1), fmaxf(n2, n3));
    #pragma unroll
    for (int o = 16; o; o >>= 1) mx2 = fmaxf(mx2, __shfl_xor_sync(0xffffffffu, mx2, o));
    __syncthreads();                    // sm[0..7] reuse barrier
    if (lane == 0) sm[warp] = mx2;
    __syncthreads();
    if (tid == 0) {
        float t = sm[0];
        #pragma unroll
        for (int w = 1; w < 8; w++) t = fmaxf(t, sm[w]);
        sm[35] = t;
    }
    __syncthreads();
    const float m2 = sm[35];

    float q0 = expf(n0 - m2), q1 = expf(n1 - m2), q2 = expf(n2 - m2), q3 = expf(n3 - m2);
    float z2 = q0 + q1 + q2 + q3;
    #pragma unroll
    for (int o = 16; o; o >>= 1) z2 += __shfl_xor_sync(0xffffffffu, z2, o);
    __syncthreads();                    // sm[0..7] reuse barrier
    if (lane == 0) sm[warp] = z2;
    __syncthreads();
    if (tid == 0) { float t = 0.f; for (int w = 0; w < 8; w++) t += sm[w]; sm[36] = t; }
    __syncthreads();
    const float invZ2 = 1.f / sm[36];

    float4 o4;
    o4.x = q0 * invZ2; o4.y = q1 * invZ2; o4.z = q2 * invZ2; o4.w = q3 * invZ2;
    *(float4*)(row + jb) = o4;
}

// ============================================================================
// Launch sequence
// ============================================================================
extern "C" void kernel_launch(void* const* d_in, const int* in_sizes, int n_in,
                              void* d_out, int out_size)
{
    const float* q      = (const float*)d_in[0];
    const float* k      = (const float*)d_in[1];
    const float* v      = (const float*)d_in[2];
    const float* Wq     = (const float*)d_in[3];
    const float* bq     = (const float*)d_in[4];
    const float* Wk     = (const float*)d_in[5];
    const float* bk     = (const float*)d_in[6];
    const float* Wv     = (const float*)d_in[7];
    const float* bv     = (const float*)d_in[8];
    const float* Wo     = (const float*)d_in[9];
    const float* bo     = (const float*)d_in[10];
    const float* gammas = (const float*)d_in[11];
    float* out = (float*)d_out;

    float *qh, *kh, *vh, *sc, *cc;
    cudaGetSymbolAddress((void**)&qh, g_qh);
    cudaGetSymbolAddress((void**)&kh, g_kh);
    cudaGetSymbolAddress((void**)&vh, g_vh);
    cudaGetSymbolAddress((void**)&sc, g_scores);
    cudaGetSymbolAddress((void**)&cc, g_concat);

    const dim3 blk(256);
    const int M = CB * CS;   // 4096

    // QKV projections (head-scattered outputs)
    gemm_nt_kernel<1><<<dim3(CDM/128, M/128, 1), blk>>>(q, Wq, bq, qh, M, CDM, CDM, 1.f, 0, 0, 0);
    gemm_nt_kernel<1><<<dim3(CDM/128, M/128, 1), blk>>>(k, Wk, bk, kh, M, CDM, CDM, 1.f, 0, 0, 0);
    gemm_nt_kernel<1><<<dim3(CDM/128, M/128, 1), blk>>>(v, Wv, bv, vh, M, CDM, CDM, 1.f, 0, 0, 0);

    // scores = Qh @ Kh^T / 8, batched over bh
    gemm_nt_kernel<0><<<dim3(CS/128, CS/128, CBH), blk>>>(
        qh, kh, nullptr, sc, CS, CS, CDK, 0.125f,
        (long)CS*CDK, (long)CS*CDK, (long)CS*CS);

    // per-row softmax / distance-decay / second softmax (in place)
    rowops_kernel<<<CBH * CS, blk>>>(sc, gammas);

    // attn @ V -> concat layout
    gemm_av_kernel<<<dim3(1, CS/128, CBH), blk>>>(sc, vh, cc);

    // output projection
    gemm_nt_kernel<0><<<dim3(CDM/128, M/128, 1), blk>>>(cc, Wo, bo, out, M, CDM, CDM, 1.f, 0, 0, 0);
}

// round 3
// speedup vs baseline: 1.5626x; 1.5626x over previous
#include <cuda_runtime.h>
#include <cuda_bf16.h>
#include <math.h>
#include <stdint.h>

// Problem constants
#define CB   4
#define CS   1024
#define CDM  1024
#define CH   16
#define CDK  64
#define CBH  (CB*CH)

// ---------------- scratch (device globals: allocation-free) ----------------
__device__ float g_qh[(size_t)CB*CH*CS*CDK];
__device__ float g_kh[(size_t)CB*CH*CS*CDK];
__device__ float g_vh[(size_t)CB*CH*CS*CDK];
__device__ float g_scores[(size_t)CBH*CS*CS];      // 256 MB
__device__ float g_concat[(size_t)CB*CS*CDM];

// bf16 split planes: [0..n) = hi, [n..2n) = lo
__device__ __nv_bfloat16 g_qs [2*(size_t)CB*CS*CDM];
__device__ __nv_bfloat16 g_ks [2*(size_t)CB*CS*CDM];
__device__ __nv_bfloat16 g_vs [2*(size_t)CB*CS*CDM];
__device__ __nv_bfloat16 g_ccs[2*(size_t)CB*CS*CDM];
__device__ __nv_bfloat16 g_qhs[2*(size_t)CBH*CS*CDK];
__device__ __nv_bfloat16 g_khs[2*(size_t)CBH*CS*CDK];
__device__ __nv_bfloat16 g_wqs[2*(size_t)CDM*CDM];
__device__ __nv_bfloat16 g_wks[2*(size_t)CDM*CDM];
__device__ __nv_bfloat16 g_wvs[2*(size_t)CDM*CDM];
__device__ __nv_bfloat16 g_wos[2*(size_t)CDM*CDM];

// ============================================================================
// helpers
// ============================================================================
__device__ __forceinline__ uint32_t smem_u32(const void* p) {
    uint32_t a;
    asm("{ .reg .u64 t; cvta.to.shared.u64 t, %1; cvt.u32.u64 %0, t; }"
        : "=r"(a) : "l"(p));
    return a;
}

__device__ __forceinline__ void cp_async16(uint32_t dst, const void* src) {
    asm volatile("cp.async.cg.shared.global [%0], [%1], 16;"
                 :: "r"(dst), "l"(src) : "memory");
}
__device__ __forceinline__ void cp_commit() {
    asm volatile("cp.async.commit_group;" ::: "memory");
}
template<int N>
__device__ __forceinline__ void cp_wait() {
    asm volatile("cp.async.wait_group %0;" :: "n"(N) : "memory");
}

__device__ __forceinline__ void ldm4(uint32_t* r, uint32_t addr) {
    asm volatile("ldmatrix.sync.aligned.m8n8.x4.shared.b16 {%0,%1,%2,%3}, [%4];"
                 : "=r"(r[0]), "=r"(r[1]), "=r"(r[2]), "=r"(r[3]) : "r"(addr));
}

__device__ __forceinline__ void mma_bf16(float* c, const uint32_t* a, const uint32_t* b) {
    asm volatile(
        "mma.sync.aligned.m16n8k16.row.col.f32.bf16.bf16.f32 "
        "{%0,%1,%2,%3}, {%4,%5,%6,%7}, {%8,%9}, {%0,%1,%2,%3};"
        : "+f"(c[0]), "+f"(c[1]), "+f"(c[2]), "+f"(c[3])
        : "r"(a[0]), "r"(a[1]), "r"(a[2]), "r"(a[3]), "r"(b[0]), "r"(b[1]));
}

// ============================================================================
// Split fp32 -> bf16 hi/lo planes
// ============================================================================
__global__ void split_bf16_kernel(const float* __restrict__ x,
                                  __nv_bfloat16* __restrict__ out, long n)
{
    long i = ((long)blockIdx.x * blockDim.x + threadIdx.x) * 4;
    if (i >= n) return;
    float4 v = *(const float4*)(x + i);
    float f[4] = {v.x, v.y, v.z, v.w};
    __nv_bfloat16 h[4], l[4];
    #pragma unroll
    for (int j = 0; j < 4; j++) {
        h[j] = __float2bfloat16(f[j]);
        l[j] = __float2bfloat16(f[j] - __bfloat162float(h[j]));
    }
    *(uint2*)(out + i)     = *(uint2*)h;
    *(uint2*)(out + n + i) = *(uint2*)l;
}

// ============================================================================
// HMMA GEMM (bf16-split x3 combos, fp32 accumulate):
//   C[m,n] = alpha * sum_k A[m,k]*B[n,k] (+ bias[n])
// A: hi plane at A, lo plane at A+loA (same layout); B likewise.
// Tile 128x128, BK=32, 256 threads (8 warps as 4x2, warp tile 32x64),
// cp.async double-buffered smem, ldmatrix fragments, mma.sync m16n8k16 bf16.
// Batched over blockIdx.z with element strides sA,sB,sC.
// OUT_MODE 0: row-major [M,N]; OUT_MODE 1: head scatter (b,s,h,dk).
// Requires M%128==0, N%128==0, K%64==0.
// ============================================================================
#define ROWB 80                        // padded row bytes (40 bf16)
#define PLANE 10240                    // 128 rows * 80 B
#define BUF   (4*PLANE)                // Ah, Al, Bh, Bl
#define MM_SMEM (2*BUF)                // double buffered = 81920 B

template<int OUT_MODE>
__global__ void __launch_bounds__(256, 1) mma_gemm_kernel(
    const __nv_bfloat16* __restrict__ A, long loA,
    const __nv_bfloat16* __restrict__ B, long loB,
    const float* __restrict__ bias, float* __restrict__ C,
    int M, int N, int K, float alpha,
    long sA, long sB, long sC)
{
    extern __shared__ char smem[];
    const uint32_t sbase = smem_u32(smem);

    A += (long)blockIdx.z * sA;
    B += (long)blockIdx.z * sB;
    C += (long)blockIdx.z * sC;
    const int m0 = blockIdx.y * 128;
    const int n0 = blockIdx.x * 128;

    const int tid  = threadIdx.x;
    const int warp = tid >> 5;
    const int lane = tid & 31;
    const int wm   = warp & 3;          // m-warp: 0..3 (32 rows each)
    const int wn   = warp >> 2;         // n-warp: 0..1 (64 cols each)
    const int lane8 = lane & 7;
    const int lg    = lane >> 3;        // ldmatrix group 0..3

    // global plane bases for this tile (row stride = K elements)
    const __nv_bfloat16* bases[4];
    bases[0] = A + (size_t)m0 * K;          // Ah
    bases[1] = bases[0] + loA;              // Al
    bases[2] = B + (size_t)n0 * K;          // Bh
    bases[3] = bases[2] + loB;              // Bl

    float acc[2][8][4];
    #pragma unroll
    for (int i = 0; i < 2; i++)
        #pragma unroll
        for (int j = 0; j < 8; j++)
            #pragma unroll
            for (int c = 0; c < 4; c++) acc[i][j][c] = 0.f;

    const int nch = K >> 5;             // chunks of 32 k-elems

    // ---- chunk loader: 2048 x 16B segments / 256 threads = 8 each ----
    auto load_chunk = [&](int ic, int b) {
        const int k0 = ic * 32;
        #pragma unroll
        for (int i = 0; i < 8; i++) {
            int seg = i * 256 + tid;            // 0..2047
            int p   = seg >> 9;                 // plane 0..3
            int r   = (seg >> 2) & 127;         // row 0..127
            int c   = seg & 3;                  // 16B col 0..3
            const __nv_bfloat16* src = bases[p] + (size_t)r * K + k0 + c * 8;
            uint32_t dst = sbase + b * BUF + p * PLANE + r * ROWB + c * 16;
            cp_async16(dst, src);
        }
        cp_commit();
    };

    load_chunk(0, 0);
    if (nch > 1) load_chunk(1, 1);

    for (int ic = 0; ic < nch; ic++) {
        const int b = ic & 1;
        if (ic == nch - 1) cp_wait<0>(); else cp_wait<1>();
        __syncthreads();

        const uint32_t bb = sbase + b * BUF;
        #pragma unroll
        for (int kk = 0; kk < 2; kk++) {
            // A fragments (hi & lo), 2 m16 tiles
            uint32_t ah[2][4], al[2][4];
            #pragma unroll
            for (int tm = 0; tm < 2; tm++) {
                int row = wm * 32 + tm * 16 + lane8 + (lg & 1) * 8;
                int col = kk * 32 + (lg >> 1) * 16;           // bytes
                uint32_t addr = bb + row * ROWB + col;
                ldm4(ah[tm], addr);
                ldm4(al[tm], addr + PLANE);
            }
            // B tiles: 4 pairs of n8 tiles
            #pragma unroll
            for (int tp = 0; tp < 4; tp++) {
                uint32_t bhf[4], blf[4];
                int row = wn * 64 + tp * 16 + lane8 + (lg >> 1) * 8;
                int col = kk * 32 + (lg & 1) * 16;
                uint32_t addr = bb + 2 * PLANE + row * ROWB + col;
                ldm4(bhf, addr);
                ldm4(blf, addr + PLANE);
                #pragma unroll
                for (int tm = 0; tm < 2; tm++) {
                    #pragma unroll
                    for (int h2 = 0; h2 < 2; h2++) {
                        float* c = acc[tm][tp * 2 + h2];
                        mma_bf16(c, ah[tm], bhf + h2 * 2);   // Ah*Bh
                        mma_bf16(c, ah[tm], blf + h2 * 2);   // Ah*Bl
                        mma_bf16(c, al[tm], bhf + h2 * 2);   // Al*Bh
                    }
                }
            }
        }
        __syncthreads();
        if (ic + 2 < nch) load_chunk(ic + 2, b);
    }

    // ---- epilogue ----
    const int gid = lane >> 2;
    const int tig = lane & 3;
    #pragma unroll
    for (int tm = 0; tm < 2; tm++) {
        #pragma unroll
        for (int tn = 0; tn < 8; tn++) {
            float* c = acc[tm][tn];
            const int m = m0 + wm * 32 + tm * 16 + gid;
            const int n = n0 + wn * 64 + tn * 8 + tig * 2;
            float b0 = 0.f, b1 = 0.f;
            if (bias) { b0 = bias[n]; b1 = bias[n + 1]; }
            float v00 = c[0] * alpha + b0, v01 = c[1] * alpha + b1;
            float v10 = c[2] * alpha + b0, v11 = c[3] * alpha + b1;
            if (OUT_MODE == 0) {
                *(float2*)(C + (size_t)m * N + n)       = make_float2(v00, v01);
                *(float2*)(C + (size_t)(m + 8) * N + n) = make_float2(v10, v11);
            } else {
                const int h  = n >> 6;
                const int dk = n & 63;
                {
                    const int b_ = m >> 10, s = m & 1023;
                    *(float2*)(C + (((size_t)(b_ * CH + h)) * CS + s) * CDK + dk)
                        = make_float2(v00, v01);
                }
                {
                    const int m2 = m + 8;
                    const int b_ = m2 >> 10, s = m2 & 1023;
                    *(float2*)(C + (((size_t)(b_ * CH + h)) * CS + s) * CDK + dk)
                        = make_float2(v10, v11);
                }
            }
        }
    }
}

// ============================================================================
// attn @ V (fp32 SIMT, unchanged from R1)
// ============================================================================
__global__ void __launch_bounds__(256) gemm_av_kernel(
    const float* __restrict__ P, const float* __restrict__ V,
    float* __restrict__ Cc)
{
    const int z = blockIdx.z;
    const float* Pz = P + (long)z * CS * CS;
    const float* Vz = V + (long)z * CS * CDK;
    const int m0 = blockIdx.y * 128;

    __shared__ float As[16][128];
    __shared__ float Bs[16][64];

    const int tid  = threadIdx.x;
    const int tx   = tid & 15;
    const int ty   = tid >> 4;
    const int arow = tid >> 2;
    const int ak4  = (tid & 3) << 2;
    const int brow = tid >> 4;
    const int bn4  = (tid & 15) << 2;

    float acc[8][4];
    #pragma unroll
    for (int i = 0; i < 8; i++)
        #pragma unroll
        for (int j = 0; j < 4; j++) acc[i][j] = 0.f;

    for (int k0 = 0; k0 < CS; k0 += 16) {
        float4 a0 = *(const float4*)(Pz + (long)(m0 + arow)      * CS + k0 + ak4);
        float4 a1 = *(const float4*)(Pz + (long)(m0 + arow + 64) * CS + k0 + ak4);
        float4 b0 = *(const float4*)(Vz + (long)(k0 + brow) * CDK + bn4);
        As[ak4+0][arow]    = a0.x; As[ak4+1][arow]    = a0.y;
        As[ak4+2][arow]    = a0.z; As[ak4+3][arow]    = a0.w;
        As[ak4+0][arow+64] = a1.x; As[ak4+1][arow+64] = a1.y;
        As[ak4+2][arow+64] = a1.z; As[ak4+3][arow+64] = a1.w;
        *(float4*)&Bs[brow][bn4] = b0;
        __syncthreads();
        #pragma unroll
        for (int kk = 0; kk < 16; kk++) {
            float a[8], b[4];
            *(float4*)&a[0] = *(const float4*)&As[kk][ty*4];
            *(float4*)&a[4] = *(const float4*)&As[kk][64 + ty*4];
            *(float4*)&b[0] = *(const float4*)&Bs[kk][tx*4];
            #pragma unroll
            for (int i = 0; i < 8; i++)
                #pragma unroll
                for (int j = 0; j < 4; j++)
                    acc[i][j] += a[i] * b[j];
        }
        __syncthreads();
    }

    const int b_ = z >> 4;
    const int h  = z & 15;
    #pragma unroll
    for (int i = 0; i < 8; i++) {
        int m = m0 + ((i < 4) ? (ty*4 + i) : (64 + ty*4 + i - 4));
        float* outp = Cc + ((long)(b_*CS + m)) * CDM + h * CDK;
        #pragma unroll
        for (int j = 0; j < 4; j++)
            outp[tx*4 + j] = acc[i][j];
    }
}

// ============================================================================
// Row-ops (unchanged from R1, verified correct)
// ============================================================================
__global__ void __launch_bounds__(256) rowops_kernel(
    float* __restrict__ scores, const float* __restrict__ gammas)
{
    const long gid = blockIdx.x;
    const int  i   = (int)(gid & (CS - 1));
    const int  bh  = (int)(gid >> 10);
    const int  h   = bh & (CH - 1);
    float* row = scores + gid * CS;

    const int tid  = threadIdx.x;
    const int lane = tid & 31;
    const int warp = tid >> 5;
    const int jb   = tid << 2;

    __shared__ float sm[64];

    float4 sv = *(const float4*)(row + jb);
    float s0 = sv.x, s1 = sv.y, s2 = sv.z, s3 = sv.w;

    float mx = fmaxf(fmaxf(s0, s1), fmaxf(s2, s3));
    #pragma unroll
    for (int o = 16; o; o >>= 1) mx = fmaxf(mx, __shfl_xor_sync(0xffffffffu, mx, o));
    if (lane == 0) sm[warp] = mx;
    __syncthreads();
    if (tid == 0) {
        float t = sm[0];
        #pragma unroll
        for (int w = 1; w < 8; w++) t = fmaxf(t, sm[w]);
        sm[32] = t;
    }
    __syncthreads();
    const float m = sm[32];

    float e0 = expf(s0 - m), e1 = expf(s1 - m), e2 = expf(s2 - m), e3 = expf(s3 - m);
    float zl = e0 + e1 + e2 + e3;
    #pragma unroll
    for (int o = 16; o; o >>= 1) zl += __shfl_xor_sync(0xffffffffu, zl, o);
    __syncthreads();
    if (lane == 0) sm[warp] = zl;
    __syncthreads();
    if (tid == 0) { float t = 0.f; for (int w = 0; w < 8; w++) t += sm[w]; sm[33] = t; }

    float me0 = (jb + 0 <= i) ? e0 : 0.f;
    float me1 = (jb + 1 <= i) ? e1 : 0.f;
    float me2 = (jb + 2 <= i) ? e2 : 0.f;
    float me3 = (jb + 3 <= i) ? e3 : 0.f;
    float c0 = me0, c1 = c0 + me1, c2 = c1 + me2, c3 = c2 + me3;
    float x = c3;
    #pragma unroll
    for (int d = 1; d < 32; d <<= 1) {
        float y = __shfl_up_sync(0xffffffffu, x, d);
        if (lane >= d) x += y;
    }
    if (lane == 31) sm[16 + warp] = x;
    __syncthreads();
    if (tid == 0) {
        float a = 0.f;
        #pragma unroll
        for (int w = 0; w < 8; w++) { float t = sm[16 + w]; sm[24 + w] = a; a += t; }
        sm[34] = a;
    }
    __syncthreads();
    const float Z     = sm[33];
    const float T     = sm[34];
    const float carry = sm[24 + warp] + (x - c3);
    c0 += carry; c1 += carry; c2 += carry; c3 += carry;

    const float g     = gammas[h];
    const float gamma = -((g > 20.f) ? g : log1pf(expf(g)));
    const float invZ  = 1.f / Z;
    const float NEG_INF = -__int_as_float(0x7f800000);

    float n0, n1, n2, n3;
    {
        int j;
        j = jb + 0;
        if (j <= i) {
            float d2 = fmaxf((T - c0) * invZ * (float)(i - j), 0.f);
            float eff = fminf(fmaxf(expf(gamma * sqrtf(d2)), 1e-5f), 1e5f);
            n0 = s0 * eff;
        } else n0 = NEG_INF;
        j = jb + 1;
        if (j <= i) {
            float d2 = fmaxf((T - c1) * invZ * (float)(i - j), 0.f);
            float eff = fminf(fmaxf(expf(gamma * sqrtf(d2)), 1e-5f), 1e5f);
            n1 = s1 * eff;
        } else n1 = NEG_INF;
        j = jb + 2;
        if (j <= i) {
            float d2 = fmaxf((T - c2) * invZ * (float)(i - j), 0.f);
            float eff = fminf(fmaxf(expf(gamma * sqrtf(d2)), 1e-5f), 1e5f);
            n2 = s2 * eff;
        } else n2 = NEG_INF;
        j = jb + 3;
        if (j <= i) {
            float d2 = fmaxf((T - c3) * invZ * (float)(i - j), 0.f);
            float eff = fminf(fmaxf(expf(gamma * sqrtf(d2)), 1e-5f), 1e5f);
            n3 = s3 * eff;
        } else n3 = NEG_INF;
    }

    float mx2 = fmaxf(fmaxf(n0, n1), fmaxf(n2, n3));
    #pragma unroll
    for (int o = 16; o; o >>= 1) mx2 = fmaxf(mx2, __shfl_xor_sync(0xffffffffu, mx2, o));
    __syncthreads();
    if (lane == 0) sm[warp] = mx2;
    __syncthreads();
    if (tid == 0) {
        float t = sm[0];
        #pragma unroll
        for (int w = 1; w < 8; w++) t = fmaxf(t, sm[w]);
        sm[35] = t;
    }
    __syncthreads();
    const float m2 = sm[35];

    float q0 = expf(n0 - m2), q1 = expf(n1 - m2), q2 = expf(n2 - m2), q3 = expf(n3 - m2);
    float z2 = q0 + q1 + q2 + q3;
    #pragma unroll
    for (int o = 16; o; o >>= 1) z2 += __shfl_xor_sync(0xffffffffu, z2, o);
    __syncthreads();
    if (lane == 0) sm[warp] = z2;
    __syncthreads();
    if (tid == 0) { float t = 0.f; for (int w = 0; w < 8; w++) t += sm[w]; sm[36] = t; }
    __syncthreads();
    const float invZ2 = 1.f / sm[36];

    float4 o4;
    o4.x = q0 * invZ2; o4.y = q1 * invZ2; o4.z = q2 * invZ2; o4.w = q3 * invZ2;
    *(float4*)(row + jb) = o4;
}

// ============================================================================
// Launch sequence
// ============================================================================
extern "C" void kernel_launch(void* const* d_in, const int* in_sizes, int n_in,
                              void* d_out, int out_size)
{
    const float* q      = (const float*)d_in[0];
    const float* k      = (const float*)d_in[1];
    const float* v      = (const float*)d_in[2];
    const float* Wq     = (const float*)d_in[3];
    const float* bq     = (const float*)d_in[4];
    const float* Wk     = (const float*)d_in[5];
    const float* bk     = (const float*)d_in[6];
    const float* Wv     = (const float*)d_in[7];
    const float* bv     = (const float*)d_in[8];
    const float* Wo     = (const float*)d_in[9];
    const float* bo     = (const float*)d_in[10];
    const float* gammas = (const float*)d_in[11];
    float* out = (float*)d_out;

    float *qh, *kh, *vh, *sc, *cc;
    __nv_bfloat16 *qs, *ks, *vs, *ccs, *qhs, *khs, *wqs, *wks, *wvs, *wos;
    cudaGetSymbolAddress((void**)&qh, g_qh);
    cudaGetSymbolAddress((void**)&kh, g_kh);
    cudaGetSymbolAddress((void**)&vh, g_vh);
    cudaGetSymbolAddress((void**)&sc, g_scores);
    cudaGetSymbolAddress((void**)&cc, g_concat);
    cudaGetSymbolAddress((void**)&qs,  g_qs);
    cudaGetSymbolAddress((void**)&ks,  g_ks);
    cudaGetSymbolAddress((void**)&vs,  g_vs);
    cudaGetSymbolAddress((void**)&ccs, g_ccs);
    cudaGetSymbolAddress((void**)&qhs, g_qhs);
    cudaGetSymbolAddress((void**)&khs, g_khs);
    cudaGetSymbolAddress((void**)&wqs, g_wqs);
    cudaGetSymbolAddress((void**)&wks, g_wks);
    cudaGetSymbolAddress((void**)&wvs, g_wvs);
    cudaGetSymbolAddress((void**)&wos, g_wos);

    cudaFuncSetAttribute(mma_gemm_kernel<0>, cudaFuncAttributeMaxDynamicSharedMemorySize, MM_SMEM);
    cudaFuncSetAttribute(mma_gemm_kernel<1>, cudaFuncAttributeMaxDynamicSharedMemorySize, MM_SMEM);

    const int  M    = CB * CS;              // 4096
    const long nBig = (long)M * CDM;        // 4 M elems
    const long nW   = (long)CDM * CDM;      // 1 M elems
    const long nH   = (long)CBH * CS * CDK; // 4 M elems

    // split inputs + weights to bf16 hi/lo planes
    split_bf16_kernel<<<(unsigned)(nBig/1024), 256>>>(q,  qs,  nBig);
    split_bf16_kernel<<<(unsigned)(nBig/1024), 256>>>(k,  ks,  nBig);
    split_bf16_kernel<<<(unsigned)(nBig/1024), 256>>>(v,  vs,  nBig);
    split_bf16_kernel<<<(unsigned)(nW/1024),   256>>>(Wq, wqs, nW);
    split_bf16_kernel<<<(unsigned)(nW/1024),   256>>>(Wk, wks, nW);
    split_bf16_kernel<<<(unsigned)(nW/1024),   256>>>(Wv, wvs, nW);
    split_bf16_kernel<<<(unsigned)(nW/1024),   256>>>(Wo, wos, nW);

    // QKV projections on tensor cores (head-scattered fp32 outputs)
    mma_gemm_kernel<1><<<dim3(CDM/128, M/128), 256, MM_SMEM>>>(
        qs, nBig, wqs, nW, bq, qh, M, CDM, CDM, 1.f, 0, 0, 0);
    mma_gemm_kernel<1><<<dim3(CDM/128, M/128), 256, MM_SMEM>>>(
        ks, nBig, wks, nW, bk, kh, M, CDM, CDM, 1.f, 0, 0, 0);
    mma_gemm_kernel<1><<<dim3(CDM/128, M/128), 256, MM_SMEM>>>(
        vs, nBig, wvs, nW, bv, vh, M, CDM, CDM, 1.f, 0, 0, 0);

    // split qh/kh for tensor-core QK^T
    split_bf16_kernel<<<(unsigned)(nH/1024), 256>>>(qh, qhs, nH);
    split_bf16_kernel<<<(unsigned)(nH/1024), 256>>>(kh, khs, nH);

    // scores = Qh @ Kh^T / 8, batched over bh
    mma_gemm_kernel<0><<<dim3(CS/128, CS/128, CBH), 256, MM_SMEM>>>(
        qhs, nH, khs, nH, nullptr, sc, CS, CS, CDK, 0.125f,
        (long)CS*CDK, (long)CS*CDK, (long)CS*CS);

    rowops_kernel<<<CBH * CS, 256>>>(sc, gammas);

    gemm_av_kernel<<<dim3(1, CS/128, CBH), 256>>>(sc, vh, cc);

    // split concat, then output projection on tensor cores
    split_bf16_kernel<<<(unsigned)(nBig/1024), 256>>>(cc, ccs, nBig);
    mma_gemm_kernel<0><<<dim3(CDM/128, M/128), 256, MM_SMEM>>>(
        ccs, nBig, wos, nW, bo, out, M, CDM, CDM, 1.f, 0, 0, 0);
}

// round 4
// speedup vs baseline: 2.0067x; 1.2841x over previous
#include <cuda_runtime.h>
#include <cuda_bf16.h>
#include <cuda_fp16.h>
#include <math.h>
#include <stdint.h>

// Problem constants
#define CB   4
#define CS   1024
#define CDM  1024
#define CH   16
#define CDK  64
#define CBH  (CB*CH)

// ---------------- scratch (device globals: allocation-free) ----------------
__device__ float g_scores[(size_t)CBH*CS*CS];            // 256 MB fp32
__device__ __half g_ps [(size_t)CBH*CS*CS];              // 128 MB fp16 (P)
__device__ __half g_vts[2*(size_t)CBH*CDK*CS];           // V^T fp16 hi/lo
__device__ __nv_bfloat16 g_qs [2*(size_t)CB*CS*CDM];
__device__ __nv_bfloat16 g_ks [2*(size_t)CB*CS*CDM];
__device__ __nv_bfloat16 g_vs [2*(size_t)CB*CS*CDM];
__device__ __nv_bfloat16 g_ccs[2*(size_t)CB*CS*CDM];
__device__ __nv_bfloat16 g_qhs[2*(size_t)CBH*CS*CDK];
__device__ __nv_bfloat16 g_khs[2*(size_t)CBH*CS*CDK];
__device__ __nv_bfloat16 g_wqs[2*(size_t)CDM*CDM];
__device__ __nv_bfloat16 g_wks[2*(size_t)CDM*CDM];
__device__ __nv_bfloat16 g_wvs[2*(size_t)CDM*CDM];
__device__ __nv_bfloat16 g_wos[2*(size_t)CDM*CDM];

// ============================================================================
// helpers
// ============================================================================
__device__ __forceinline__ uint32_t smem_u32(const void* p) {
    uint32_t a;
    asm("{ .reg .u64 t; cvta.to.shared.u64 t, %1; cvt.u32.u64 %0, t; }"
        : "=r"(a) : "l"(p));
    return a;
}
__device__ __forceinline__ void cp_async16(uint32_t dst, const void* src) {
    asm volatile("cp.async.cg.shared.global [%0], [%1], 16;"
                 :: "r"(dst), "l"(src) : "memory");
}
__device__ __forceinline__ void cp_commit() {
    asm volatile("cp.async.commit_group;" ::: "memory");
}
template<int N>
__device__ __forceinline__ void cp_wait() {
    asm volatile("cp.async.wait_group %0;" :: "n"(N) : "memory");
}
__device__ __forceinline__ void ldm4(uint32_t* r, uint32_t addr) {
    asm volatile("ldmatrix.sync.aligned.m8n8.x4.shared.b16 {%0,%1,%2,%3}, [%4];"
                 : "=r"(r[0]), "=r"(r[1]), "=r"(r[2]), "=r"(r[3]) : "r"(addr));
}
__device__ __forceinline__ void mma_bf16(float* c, const uint32_t* a, const uint32_t* b) {
    asm volatile(
        "mma.sync.aligned.m16n8k16.row.col.f32.bf16.bf16.f32 "
        "{%0,%1,%2,%3}, {%4,%5,%6,%7}, {%8,%9}, {%0,%1,%2,%3};"
        : "+f"(c[0]), "+f"(c[1]), "+f"(c[2]), "+f"(c[3])
        : "r"(a[0]), "r"(a[1]), "r"(a[2]), "r"(a[3]), "r"(b[0]), "r"(b[1]));
}
__device__ __forceinline__ void mma_f16(float* c, const uint32_t* a, const uint32_t* b) {
    asm volatile(
        "mma.sync.aligned.m16n8k16.row.col.f32.f16.f16.f32 "
        "{%0,%1,%2,%3}, {%4,%5,%6,%7}, {%8,%9}, {%0,%1,%2,%3};"
        : "+f"(c[0]), "+f"(c[1]), "+f"(c[2]), "+f"(c[3])
        : "r"(a[0]), "r"(a[1]), "r"(a[2]), "r"(a[3]), "r"(b[0]), "r"(b[1]));
}

// ============================================================================
// Split fp32 -> bf16 hi/lo planes
// ============================================================================
__global__ void split_bf16_kernel(const float* __restrict__ x,
                                  __nv_bfloat16* __restrict__ out, long n)
{
    long i = ((long)blockIdx.x * blockDim.x + threadIdx.x) * 4;
    if (i >= n) return;
    float4 v = *(const float4*)(x + i);
    float f[4] = {v.x, v.y, v.z, v.w};
    __nv_bfloat16 h[4], l[4];
    #pragma unroll
    for (int j = 0; j < 4; j++) {
        h[j] = __float2bfloat16(f[j]);
        l[j] = __float2bfloat16(f[j] - __bfloat162float(h[j]));
    }
    *(uint2*)(out + i)     = *(uint2*)h;
    *(uint2*)(out + n + i) = *(uint2*)l;
}

// ============================================================================
// HMMA GEMM (bf16-split x3 combos, fp32 accumulate):
//   C[m,n] = alpha * sum_k A[m,k]*B[n,k] (+ bias[n])
// OUT_MODE 0: fp32 row-major [M,N] -> C
// OUT_MODE 2: bf16 hi/lo planes, head-scatter [(b*H+h)*S+s]*DK+dk -> Cpl (+PL)
// OUT_MODE 3: fp16 hi/lo planes, transposed head-scatter
//             [((b*H+h)*DK+dk)*S+s] -> Cpl (+PL)
// ============================================================================
#define ROWB 80
#define PLANE 10240
#define BUF   (4*PLANE)
#define MM_SMEM (2*BUF)

template<int OUT_MODE>
__global__ void __launch_bounds__(256, 1) mma_gemm_kernel(
    const __nv_bfloat16* __restrict__ A, long loA,
    const __nv_bfloat16* __restrict__ B, long loB,
    const float* __restrict__ bias, float* __restrict__ C,
    void* __restrict__ Cpl, long PL,
    int M, int N, int K, float alpha,
    long sA, long sB, long sC)
{
    extern __shared__ char smem[];
    const uint32_t sbase = smem_u32(smem);

    A += (long)blockIdx.z * sA;
    B += (long)blockIdx.z * sB;
    C += (long)blockIdx.z * sC;
    const int m0 = blockIdx.y * 128;
    const int n0 = blockIdx.x * 128;

    const int tid  = threadIdx.x;
    const int warp = tid >> 5;
    const int lane = tid & 31;
    const int wm   = warp & 3;
    const int wn   = warp >> 2;
    const int lane8 = lane & 7;
    const int lg    = lane >> 3;

    const __nv_bfloat16* bases[4];
    bases[0] = A + (size_t)m0 * K;
    bases[1] = bases[0] + loA;
    bases[2] = B + (size_t)n0 * K;
    bases[3] = bases[2] + loB;

    float acc[2][8][4];
    #pragma unroll
    for (int i = 0; i < 2; i++)
        #pragma unroll
        for (int j = 0; j < 8; j++)
            #pragma unroll
            for (int c = 0; c < 4; c++) acc[i][j][c] = 0.f;

    const int nch = K >> 5;

    auto load_chunk = [&](int ic, int b) {
        const int k0 = ic * 32;
        #pragma unroll
        for (int i = 0; i < 8; i++) {
            int seg = i * 256 + tid;
            int p   = seg >> 9;
            int r   = (seg >> 2) & 127;
            int c   = seg & 3;
            const __nv_bfloat16* src = bases[p] + (size_t)r * K + k0 + c * 8;
            uint32_t dst = sbase + b * BUF + p * PLANE + r * ROWB + c * 16;
            cp_async16(dst, src);
        }
        cp_commit();
    };

    load_chunk(0, 0);
    if (nch > 1) load_chunk(1, 1);

    for (int ic = 0; ic < nch; ic++) {
        const int b = ic & 1;
        if (ic == nch - 1) cp_wait<0>(); else cp_wait<1>();
        __syncthreads();

        const uint32_t bb = sbase + b * BUF;
        #pragma unroll
        for (int kk = 0; kk < 2; kk++) {
            uint32_t ah[2][4], al[2][4];
            #pragma unroll
            for (int tm = 0; tm < 2; tm++) {
                int row = wm * 32 + tm * 16 + lane8 + (lg & 1) * 8;
                int col = kk * 32 + (lg >> 1) * 16;
                uint32_t addr = bb + row * ROWB + col;
                ldm4(ah[tm], addr);
                ldm4(al[tm], addr + PLANE);
            }
            #pragma unroll
            for (int tp = 0; tp < 4; tp++) {
                uint32_t bhf[4], blf[4];
                int row = wn * 64 + tp * 16 + lane8 + (lg >> 1) * 8;
                int col = kk * 32 + (lg & 1) * 16;
                uint32_t addr = bb + 2 * PLANE + row * ROWB + col;
                ldm4(bhf, addr);
                ldm4(blf, addr + PLANE);
                #pragma unroll
                for (int tm = 0; tm < 2; tm++) {
                    #pragma unroll
                    for (int h2 = 0; h2 < 2; h2++) {
                        float* c = acc[tm][tp * 2 + h2];
                        mma_bf16(c, ah[tm], bhf + h2 * 2);
                        mma_bf16(c, ah[tm], blf + h2 * 2);
                        mma_bf16(c, al[tm], bhf + h2 * 2);
                    }
                }
            }
        }
        __syncthreads();
        if (ic + 2 < nch) load_chunk(ic + 2, b);
    }

    // ---- epilogue ----
    const int gid = lane >> 2;
    const int tig = lane & 3;
    #pragma unroll
    for (int tm = 0; tm < 2; tm++) {
        #pragma unroll
        for (int tn = 0; tn < 8; tn++) {
            float* c = acc[tm][tn];
            const int m = m0 + wm * 32 + tm * 16 + gid;
            const int n = n0 + wn * 64 + tn * 8 + tig * 2;
            float b0 = 0.f, b1 = 0.f;
            if (bias) { b0 = bias[n]; b1 = bias[n + 1]; }
            float v00 = c[0] * alpha + b0, v01 = c[1] * alpha + b1;
            float v10 = c[2] * alpha + b0, v11 = c[3] * alpha + b1;
            if (OUT_MODE == 0) {
                *(float2*)(C + (size_t)m * N + n)       = make_float2(v00, v01);
                *(float2*)(C + (size_t)(m + 8) * N + n) = make_float2(v10, v11);
            } else if (OUT_MODE == 2) {
                __nv_bfloat16* P = (__nv_bfloat16*)Cpl;
                const int h  = n >> 6;
                const int dk = n & 63;
                #pragma unroll
                for (int rr = 0; rr < 2; rr++) {
                    const int mm = m + rr * 8;
                    const float va = rr ? v10 : v00, vb = rr ? v11 : v01;
                    const int b_ = mm >> 10, s = mm & 1023;
                    size_t idx = (((size_t)(b_ * CH + h)) * CS + s) * CDK + dk;
                    __nv_bfloat16 h2[2], l2[2];
                    h2[0] = __float2bfloat16(va);
                    h2[1] = __float2bfloat16(vb);
                    l2[0] = __float2bfloat16(va - __bfloat162float(h2[0]));
                    l2[1] = __float2bfloat16(vb - __bfloat162float(h2[1]));
                    *(uint32_t*)(P + idx)      = *(uint32_t*)h2;
                    *(uint32_t*)(P + PL + idx) = *(uint32_t*)l2;
                }
            } else { // OUT_MODE 3: fp16 transposed planes
                __half* P = (__half*)Cpl;
                const int h  = n >> 6;
                const int dk = n & 63;
                #pragma unroll
                for (int rr = 0; rr < 2; rr++) {
                    const int mm = m + rr * 8;
                    const float va = rr ? v10 : v00, vb = rr ? v11 : v01;
                    const int b_ = mm >> 10, s = mm & 1023;
                    size_t base = (((size_t)(b_ * CH + h)) * CDK + dk) * CS + s;
                    __half ha = __float2half(va);
                    __half la = __float2half(va - __half2float(ha));
                    __half hb = __float2half(vb);
                    __half lb = __float2half(vb - __half2float(hb));
                    P[base]           = ha;
                    P[base + PL]      = la;
                    P[base + CS]      = hb;
                    P[base + CS + PL] = lb;
                }
            }
        }
    }
}

// ============================================================================
// AV HMMA: O[bh][i][d] = sum_j P[bh][i][j] * Vt[bh][d][j]
// P fp16 single plane; Vt fp16 hi/lo planes (+PLV). Tile 128m x 64n, BK=64.
// 8 warps as 4m x 2n, warp tile 32x32. Writes concat bf16 hi/lo planes.
// ============================================================================
#define AROWB 144                      // 64 fp16 = 128B + 16 pad
#define AP_BYTES (128*AROWB)           // P tile 18432
#define AV_BYTES (2*64*AROWB)          // V hi+lo 18432
#define AV_BUF (AP_BYTES + AV_BYTES)
#define AV_SMEM (2*AV_BUF)             // 73728

__global__ void __launch_bounds__(256, 1) av_mma_kernel(
    const __half* __restrict__ Pg, const __half* __restrict__ Vt, long PLV,
    __nv_bfloat16* __restrict__ Cc, long PLC)
{
    extern __shared__ char smem[];
    const uint32_t sbase = smem_u32(smem);

    const int z  = blockIdx.z;                         // bh
    const int m0 = blockIdx.y * 128;
    const __half* Pz = Pg + (size_t)z * CS * CS;
    const __half* Vz = Vt + (size_t)z * CDK * CS;

    const int tid  = threadIdx.x;
    const int warp = tid >> 5;
    const int lane = tid & 31;
    const int wm   = warp & 3;          // 4 m-warps of 32
    const int wn   = warp >> 2;         // 2 n-warps of 32
    const int lane8 = lane & 7;
    const int lg    = lane >> 3;

    float acc[2][4][4];
    #pragma unroll
    for (int i = 0; i < 2; i++)
        #pragma unroll
        for (int j = 0; j < 4; j++)
            #pragma unroll
            for (int c = 0; c < 4; c++) acc[i][j][c] = 0.f;

    const int nch = CS >> 6;            // 16 chunks of 64

    auto load_chunk = [&](int ic, int b) {
        const int k0 = ic * 64;
        #pragma unroll
        for (int i = 0; i < 8; i++) {
            int seg = i * 256 + tid;            // 0..2047
            int part = seg >> 10;               // 0 = P, 1 = V
            int r    = (seg >> 3) & 127;
            int c    = seg & 7;
            uint32_t dstb = sbase + b * AV_BUF;
            if (part == 0) {
                const __half* src = Pz + (size_t)(m0 + r) * CS + k0 + c * 8;
                cp_async16(dstb + r * AROWB + c * 16, src);
            } else {
                int pl = r >> 6, rr = r & 63;
                const __half* src = Vz + (size_t)pl * PLV + (size_t)rr * CS + k0 + c * 8;
                cp_async16(dstb + AP_BYTES + pl * (64 * AROWB) + rr * AROWB + c * 16, src);
            }
        }
        cp_commit();
    };

    load_chunk(0, 0);
    load_chunk(1, 1);

    for (int ic = 0; ic < nch; ic++) {
        const int b = ic & 1;
        if (ic == nch - 1) cp_wait<0>(); else cp_wait<1>();
        __syncthreads();

        const uint32_t bb = sbase + b * AV_BUF;
        #pragma unroll
        for (int kk = 0; kk < 4; kk++) {
            uint32_t af[2][4];
            #pragma unroll
            for (int tm = 0; tm < 2; tm++) {
                int row = wm * 32 + tm * 16 + lane8 + (lg & 1) * 8;
                int col = kk * 32 + (lg >> 1) * 16;
                ldm4(af[tm], bb + row * AROWB + col);
            }
            #pragma unroll
            for (int tp = 0; tp < 2; tp++) {
                uint32_t bhf[4], blf[4];
                int row = wn * 32 + tp * 16 + lane8 + (lg >> 1) * 8;
                int col = kk * 32 + (lg & 1) * 16;
                uint32_t addr = bb + AP_BYTES + row * AROWB + col;
                ldm4(bhf, addr);
                ldm4(blf, addr + 64 * AROWB);
                #pragma unroll
                for (int tm = 0; tm < 2; tm++) {
                    #pragma unroll
                    for (int h2 = 0; h2 < 2; h2++) {
                        float* c = acc[tm][tp * 2 + h2];
                        mma_f16(c, af[tm], bhf + h2 * 2);
                        mma_f16(c, af[tm], blf + h2 * 2);
                    }
                }
            }
        }
        __syncthreads();
        if (ic + 2 < nch) load_chunk(ic + 2, b);
    }

    // epilogue -> concat bf16 hi/lo planes: [(b*S+s)*DM + h*64 + d]
    const int gid = lane >> 2;
    const int tig = lane & 3;
    const int b_ = z >> 4;
    const int h  = z & 15;
    #pragma unroll
    for (int tm = 0; tm < 2; tm++) {
        #pragma unroll
        for (int tn = 0; tn < 4; tn++) {
            float* c = acc[tm][tn];
            const int m = m0 + wm * 32 + tm * 16 + gid;
            const int n = wn * 32 + tn * 8 + tig * 2;          // dk
            #pragma unroll
            for (int rr = 0; rr < 2; rr++) {
                const int s = m + rr * 8;
                const float va = c[rr * 2 + 0], vb = c[rr * 2 + 1];
                size_t idx = ((size_t)(b_ * CS + s)) * CDM + h * CDK + n;
                __nv_bfloat16 h2[2], l2[2];
                h2[0] = __float2bfloat16(va);
                h2[1] = __float2bfloat16(vb);
                l2[0] = __float2bfloat16(va - __bfloat162float(h2[0]));
                l2[1] = __float2bfloat16(vb - __bfloat162float(h2[1]));
                *(uint32_t*)(Cc + idx)       = *(uint32_t*)h2;
                *(uint32_t*)(Cc + PLC + idx) = *(uint32_t*)l2;
            }
        }
    }
}

// ============================================================================
// Row-ops: reads fp32 scores, writes fp16 probabilities
// ============================================================================
__global__ void __launch_bounds__(256) rowops_kernel(
    const float* __restrict__ scores, const float* __restrict__ gammas,
    __half* __restrict__ Pout)
{
    const long gid = blockIdx.x;
    const int  i   = (int)(gid & (CS - 1));
    const int  h   = (int)((gid >> 10) & (CH - 1));
    const float* row = scores + gid * CS;

    const int tid  = threadIdx.x;
    const int lane = tid & 31;
    const int warp = tid >> 5;
    const int jb   = tid << 2;

    __shared__ float sm[64];

    float4 sv = *(const float4*)(row + jb);
    float s0 = sv.x, s1 = sv.y, s2 = sv.z, s3 = sv.w;

    float mx = fmaxf(fmaxf(s0, s1), fmaxf(s2, s3));
    #pragma unroll
    for (int o = 16; o; o >>= 1) mx = fmaxf(mx, __shfl_xor_sync(0xffffffffu, mx, o));
    if (lane == 0) sm[warp] = mx;
    __syncthreads();
    if (tid == 0) {
        float t = sm[0];
        #pragma unroll
        for (int w = 1; w < 8; w++) t = fmaxf(t, sm[w]);
        sm[32] = t;
    }
    __syncthreads();
    const float m = sm[32];

    float e0 = __expf(s0 - m), e1 = __expf(s1 - m), e2 = __expf(s2 - m), e3 = __expf(s3 - m);
    float zl = e0 + e1 + e2 + e3;
    #pragma unroll
    for (int o = 16; o; o >>= 1) zl += __shfl_xor_sync(0xffffffffu, zl, o);
    __syncthreads();
    if (lane == 0) sm[warp] = zl;
    __syncthreads();
    if (tid == 0) { float t = 0.f; for (int w = 0; w < 8; w++) t += sm[w]; sm[33] = t; }

    float me0 = (jb + 0 <= i) ? e0 : 0.f;
    float me1 = (jb + 1 <= i) ? e1 : 0.f;
    float me2 = (jb + 2 <= i) ? e2 : 0.f;
    float me3 = (jb + 3 <= i) ? e3 : 0.f;
    float c0 = me0, c1 = c0 + me1, c2 = c1 + me2, c3 = c2 + me3;
    float x = c3;
    #pragma unroll
    for (int d = 1; d < 32; d <<= 1) {
        float y = __shfl_up_sync(0xffffffffu, x, d);
        if (lane >= d) x += y;
    }
    if (lane == 31) sm[16 + warp] = x;
    __syncthreads();
    if (tid == 0) {
        float a = 0.f;
        #pragma unroll
        for (int w = 0; w < 8; w++) { float t = sm[16 + w]; sm[24 + w] = a; a += t; }
        sm[34] = a;
    }
    __syncthreads();
    const float Z     = sm[33];
    const float T     = sm[34];
    const float carry = sm[24 + warp] + (x - c3);
    c0 += carry; c1 += carry; c2 += carry; c3 += carry;

    const float g     = gammas[h];
    const float gamma = -((g > 20.f) ? g : log1pf(__expf(g)));
    const float invZ  = 1.f / Z;
    const float NEG_INF = -__int_as_float(0x7f800000);

    float n0, n1, n2, n3;
    {
        int j;
        j = jb + 0;
        if (j <= i) {
            float d2 = fmaxf((T - c0) * invZ * (float)(i - j), 0.f);
            float eff = fminf(fmaxf(__expf(gamma * sqrtf(d2)), 1e-5f), 1e5f);
            n0 = s0 * eff;
        } else n0 = NEG_INF;
        j = jb + 1;
        if (j <= i) {
            float d2 = fmaxf((T - c1) * invZ * (float)(i - j), 0.f);
            float eff = fminf(fmaxf(__expf(gamma * sqrtf(d2)), 1e-5f), 1e5f);
            n1 = s1 * eff;
        } else n1 = NEG_INF;
        j = jb + 2;
        if (j <= i) {
            float d2 = fmaxf((T - c2) * invZ * (float)(i - j), 0.f);
            float eff = fminf(fmaxf(__expf(gamma * sqrtf(d2)), 1e-5f), 1e5f);
            n2 = s2 * eff;
        } else n2 = NEG_INF;
        j = jb + 3;
        if (j <= i) {
            float d2 = fmaxf((T - c3) * invZ * (float)(i - j), 0.f);
            float eff = fminf(fmaxf(__expf(gamma * sqrtf(d2)), 1e-5f), 1e5f);
            n3 = s3 * eff;
        } else n3 = NEG_INF;
    }

    float mx2 = fmaxf(fmaxf(n0, n1), fmaxf(n2, n3));
    #pragma unroll
    for (int o = 16; o; o >>= 1) mx2 = fmaxf(mx2, __shfl_xor_sync(0xffffffffu, mx2, o));
    __syncthreads();
    if (lane == 0) sm[warp] = mx2;
    __syncthreads();
    if (tid == 0) {
        float t = sm[0];
        #pragma unroll
        for (int w = 1; w < 8; w++) t = fmaxf(t, sm[w]);
        sm[35] = t;
    }
    __syncthreads();
    const float m2 = sm[35];

    float q0 = __expf(n0 - m2), q1 = __expf(n1 - m2), q2 = __expf(n2 - m2), q3 = __expf(n3 - m2);
    float z2 = q0 + q1 + q2 + q3;
    #pragma unroll
    for (int o = 16; o; o >>= 1) z2 += __shfl_xor_sync(0xffffffffu, z2, o);
    __syncthreads();
    if (lane == 0) sm[warp] = z2;
    __syncthreads();
    if (tid == 0) { float t = 0.f; for (int w = 0; w < 8; w++) t += sm[w]; sm[36] = t; }
    __syncthreads();
    const float invZ2 = 1.f / sm[36];

    __half2 p01 = __floats2half2_rn(q0 * invZ2, q1 * invZ2);
    __half2 p23 = __floats2half2_rn(q2 * invZ2, q3 * invZ2);
    __half2* outp = (__half2*)(Pout + gid * CS + jb);
    outp[0] = p01;
    outp[1] = p23;
}

// ============================================================================
// Launch sequence
// ============================================================================
extern "C" void kernel_launch(void* const* d_in, const int* in_sizes, int n_in,
                              void* d_out, int out_size)
{
    const float* q      = (const float*)d_in[0];
    const float* k      = (const float*)d_in[1];
    const float* v      = (const float*)d_in[2];
    const float* Wq     = (const float*)d_in[3];
    const float* bq     = (const float*)d_in[4];
    const float* Wk     = (const float*)d_in[5];
    const float* bk     = (const float*)d_in[6];
    const float* Wv     = (const float*)d_in[7];
    const float* bv     = (const float*)d_in[8];
    const float* Wo     = (const float*)d_in[9];
    const float* bo     = (const float*)d_in[10];
    const float* gammas = (const float*)d_in[11];
    float* out = (float*)d_out;

    float *sc;
    __half *ps, *vts;
    __nv_bfloat16 *qs, *ks, *vs, *ccs, *qhs, *khs, *wqs, *wks, *wvs, *wos;
    cudaGetSymbolAddress((void**)&sc,  g_scores);
    cudaGetSymbolAddress((void**)&ps,  g_ps);
    cudaGetSymbolAddress((void**)&vts, g_vts);
    cudaGetSymbolAddress((void**)&qs,  g_qs);
    cudaGetSymbolAddress((void**)&ks,  g_ks);
    cudaGetSymbolAddress((void**)&vs,  g_vs);
    cudaGetSymbolAddress((void**)&ccs, g_ccs);
    cudaGetSymbolAddress((void**)&qhs, g_qhs);
    cudaGetSymbolAddress((void**)&khs, g_khs);
    cudaGetSymbolAddress((void**)&wqs, g_wqs);
    cudaGetSymbolAddress((void**)&wks, g_wks);
    cudaGetSymbolAddress((void**)&wvs, g_wvs);
    cudaGetSymbolAddress((void**)&wos, g_wos);

    cudaFuncSetAttribute(mma_gemm_kernel<0>, cudaFuncAttributeMaxDynamicSharedMemorySize, MM_SMEM);
    cudaFuncSetAttribute(mma_gemm_kernel<2>, cudaFuncAttributeMaxDynamicSharedMemorySize, MM_SMEM);
    cudaFuncSetAttribute(mma_gemm_kernel<3>, cudaFuncAttributeMaxDynamicSharedMemorySize, MM_SMEM);
    cudaFuncSetAttribute(av_mma_kernel, cudaFuncAttributeMaxDynamicSharedMemorySize, AV_SMEM);

    const int  M    = CB * CS;              // 4096
    const long nBig = (long)M * CDM;        // 4 M elems
    const long nW   = (long)CDM * CDM;      // 1 M elems
    const long nH   = (long)CBH * CS * CDK; // 4 M elems

    // split inputs + weights to bf16 hi/lo planes
    split_bf16_kernel<<<(unsigned)(nBig/1024), 256>>>(q,  qs,  nBig);
    split_bf16_kernel<<<(unsigned)(nBig/1024), 256>>>(k,  ks,  nBig);
    split_bf16_kernel<<<(unsigned)(nBig/1024), 256>>>(v,  vs,  nBig);
    split_bf16_kernel<<<(unsigned)(nW/1024),   256>>>(Wq, wqs, nW);
    split_bf16_kernel<<<(unsigned)(nW/1024),   256>>>(Wk, wks, nW);
    split_bf16_kernel<<<(unsigned)(nW/1024),   256>>>(Wv, wvs, nW);
    split_bf16_kernel<<<(unsigned)(nW/1024),   256>>>(Wo, wos, nW);

    // Q/K projections -> bf16 split planes (head-scattered)
    mma_gemm_kernel<2><<<dim3(CDM/128, M/128), 256, MM_SMEM>>>(
        qs, nBig, wqs, nW, bq, nullptr, qhs, nH, M, CDM, CDM, 1.f, 0, 0, 0);
    mma_gemm_kernel<2><<<dim3(CDM/128, M/128), 256, MM_SMEM>>>(
        ks, nBig, wks, nW, bk, nullptr, khs, nH, M, CDM, CDM, 1.f, 0, 0, 0);
    // V projection -> fp16 split planes, transposed per head
    mma_gemm_kernel<3><<<dim3(CDM/128, M/128), 256, MM_SMEM>>>(
        vs, nBig, wvs, nW, bv, nullptr, vts, nH, M, CDM, CDM, 1.f, 0, 0, 0);

    // scores = Qh @ Kh^T / 8 (fp32), batched over bh
    mma_gemm_kernel<0><<<dim3(CS/128, CS/128, CBH), 256, MM_SMEM>>>(
        qhs, nH, khs, nH, nullptr, sc, nullptr, 0, CS, CS, CDK, 0.125f,
        (long)CS*CDK, (long)CS*CDK, (long)CS*CS);

    // row ops -> fp16 probabilities
    rowops_kernel<<<CBH * CS, 256>>>(sc, gammas, ps);

    // AV on tensor cores -> concat bf16 split planes
    av_mma_kernel<<<dim3(1, CS/128, CBH), 256, AV_SMEM>>>(ps, vts, nH, ccs, nBig);

    // output projection
    mma_gemm_kernel<0><<<dim3(CDM/128, M/128), 256, MM_SMEM>>>(
        ccs, nBig, wos, nW, bo, out, nullptr, 0, M, CDM, CDM, 1.f, 0, 0, 0);
}